// round 1
// baseline (speedup 1.0000x reference)
#include <cuda_runtime.h>
#include <math.h>

// Problem constants (fixed by the reference)
#define DIN   256     // input feature dim
#define HCc   256     // H1*C1 = hidden dim
#define H1n   4
#define C1n   64
#define NEG   0.2f
#define MAXN  50000

// ---------------- scratch (static device globals: allowed) ----------------
__device__ float g_XL1[(long long)MAXN * HCc];   // x @ W1l + b1l
__device__ float g_XR1[(long long)MAXN * HCc];   // x @ W1r + b1r
__device__ float g_SKIP[(long long)MAXN * HCc];  // x @ Wskip + bskip
__device__ float g_ACC1[(long long)MAXN * HCc];  // sum_e exp(l)*xl[src]
__device__ float g_DEN1[MAXN * H1n];             // sum_e exp(l)
__device__ float g_XL2[MAXN * 2];
__device__ float g_XR2[MAXN * 2];
__device__ float g_ACC2[MAXN * 2];
__device__ float g_DEN2[MAXN];
__device__ int   g_is64;

// ---------------- dtype detection for edge_index (int32 vs int64) --------
__global__ void detect_idx_kernel(const unsigned int* __restrict__ w) {
    // int64 little-endian: every odd 32-bit word is the (zero) high half.
    // int32: odd words are random node ids in [0,50000) -> ~never all zero.
    int ok = 1;
    #pragma unroll
    for (int i = 0; i < 32; i++) {
        if (w[2 * i + 1] != 0u) { ok = 0; break; }
    }
    g_is64 = ok;
}

__device__ __forceinline__ int ld_idx(const void* ei, long long pos, int is64) {
    if (is64) return (int)(((const long long*)ei)[pos]);
    return ((const int*)ei)[pos];
}

// ---------------- SGEMM: C[M,Nc] = A[M,K] @ B[K,Nc] + bias ----------------
#define BM 128
#define BN 64
#define BK 16
__global__ __launch_bounds__(256) void sgemm_bias_kernel(
    const float* __restrict__ A, const float* __restrict__ B,
    const float* __restrict__ bias, float* __restrict__ C,
    int M, int Nc, int K)
{
    __shared__ float As[BK][BM];
    __shared__ float Bs[BK][BN];
    const int tid = threadIdx.x;
    const int m0 = blockIdx.y * BM;
    const int n0 = blockIdx.x * BN;
    const int tm = tid >> 4;   // 0..15 -> 8 rows each
    const int tn = tid & 15;   // 0..15 -> 4 cols each

    float acc[8][4];
    #pragma unroll
    for (int i = 0; i < 8; i++)
        #pragma unroll
        for (int j = 0; j < 4; j++) acc[i][j] = 0.f;

    for (int k0 = 0; k0 < K; k0 += BK) {
        // load A tile: 128x16 = 512 float4
        #pragma unroll
        for (int it = 0; it < 2; it++) {
            int lin = tid + it * 256;
            int row = lin >> 2;
            int kq  = (lin & 3) * 4;
            float4 v = make_float4(0.f, 0.f, 0.f, 0.f);
            if (m0 + row < M)
                v = *(const float4*)(A + (long long)(m0 + row) * K + k0 + kq);
            As[kq + 0][row] = v.x; As[kq + 1][row] = v.y;
            As[kq + 2][row] = v.z; As[kq + 3][row] = v.w;
        }
        // load B tile: 16x64 = 256 float4
        {
            int row = tid >> 4;
            int cq  = (tid & 15) * 4;
            float4 v = *(const float4*)(B + (long long)(k0 + row) * Nc + n0 + cq);
            *(float4*)&Bs[row][cq] = v;
        }
        __syncthreads();
        #pragma unroll
        for (int k = 0; k < BK; k++) {
            float4 a0 = *(const float4*)&As[k][tm * 8];
            float4 a1 = *(const float4*)&As[k][tm * 8 + 4];
            float4 b  = *(const float4*)&Bs[k][tn * 4];
            float av[8] = {a0.x, a0.y, a0.z, a0.w, a1.x, a1.y, a1.z, a1.w};
            float bv[4] = {b.x, b.y, b.z, b.w};
            #pragma unroll
            for (int i = 0; i < 8; i++)
                #pragma unroll
                for (int j = 0; j < 4; j++)
                    acc[i][j] = fmaf(av[i], bv[j], acc[i][j]);
        }
        __syncthreads();
    }

    const int c0 = n0 + tn * 4;
    float4 bv = *(const float4*)(bias + c0);
    #pragma unroll
    for (int i = 0; i < 8; i++) {
        int m = m0 + tm * 8 + i;
        if (m < M) {
            float4 o;
            o.x = acc[i][0] + bv.x; o.y = acc[i][1] + bv.y;
            o.z = acc[i][2] + bv.z; o.w = acc[i][3] + bv.w;
            *(float4*)(C + (long long)m * Nc + c0) = o;
        }
    }
}

// ------------- conv1 self-loop init (non-atomic; one warp / node) --------
__global__ void conv1_selfloop_kernel(const float* __restrict__ att1, int N) {
    long long wid = ((long long)blockIdx.x * blockDim.x + threadIdx.x) >> 5;
    int lane = threadIdx.x & 31;
    if (wid >= N) return;
    const float* xl = g_XL1 + wid * HCc;
    const float* xr = g_XR1 + wid * HCc;
    float4 xl0 = *(const float4*)(xl + lane * 8);
    float4 xl1 = *(const float4*)(xl + lane * 8 + 4);
    float4 xr0 = *(const float4*)(xr + lane * 8);
    float4 xr1 = *(const float4*)(xr + lane * 8 + 4);
    float xlv[8] = {xl0.x, xl0.y, xl0.z, xl0.w, xl1.x, xl1.y, xl1.z, xl1.w};
    float xrv[8] = {xr0.x, xr0.y, xr0.z, xr0.w, xr1.x, xr1.y, xr1.z, xr1.w};
    float s = 0.f;
    #pragma unroll
    for (int j = 0; j < 8; j++) {
        float e = xlv[j] + xrv[j];
        e = e > 0.f ? e : NEG * e;
        s += e * att1[lane * 8 + j];
    }
    s += __shfl_xor_sync(0xffffffffu, s, 1);
    s += __shfl_xor_sync(0xffffffffu, s, 2);
    s += __shfl_xor_sync(0xffffffffu, s, 4);
    float ex = expf(s);
    if ((lane & 7) == 0) g_DEN1[wid * H1n + (lane >> 3)] = ex;
    float* op = g_ACC1 + wid * HCc + lane * 8;
    float4 o0, o1;
    o0.x = ex * xlv[0]; o0.y = ex * xlv[1]; o0.z = ex * xlv[2]; o0.w = ex * xlv[3];
    o1.x = ex * xlv[4]; o1.y = ex * xlv[5]; o1.z = ex * xlv[6]; o1.w = ex * xlv[7];
    *(float4*)(op) = o0;
    *(float4*)(op + 4) = o1;
}

// ------------- conv1 edge pass (one warp / edge, atomic accumulate) ------
__global__ void conv1_edge_kernel(const void* __restrict__ ei,
                                  const float* __restrict__ att1,
                                  long long E) {
    long long wid = ((long long)blockIdx.x * blockDim.x + threadIdx.x) >> 5;
    int lane = threadIdx.x & 31;
    if (wid >= E) return;
    int is64 = g_is64;
    int src = ld_idx(ei, wid, is64);
    int dst = ld_idx(ei, E + wid, is64);
    const float* xl = g_XL1 + (long long)src * HCc;
    const float* xr = g_XR1 + (long long)dst * HCc;
    float4 xl0 = *(const float4*)(xl + lane * 8);
    float4 xl1 = *(const float4*)(xl + lane * 8 + 4);
    float4 xr0 = *(const float4*)(xr + lane * 8);
    float4 xr1 = *(const float4*)(xr + lane * 8 + 4);
    float xlv[8] = {xl0.x, xl0.y, xl0.z, xl0.w, xl1.x, xl1.y, xl1.z, xl1.w};
    float xrv[8] = {xr0.x, xr0.y, xr0.z, xr0.w, xr1.x, xr1.y, xr1.z, xr1.w};
    float s = 0.f;
    #pragma unroll
    for (int j = 0; j < 8; j++) {
        float e = xlv[j] + xrv[j];
        e = e > 0.f ? e : NEG * e;
        s += e * att1[lane * 8 + j];
    }
    s += __shfl_xor_sync(0xffffffffu, s, 1);
    s += __shfl_xor_sync(0xffffffffu, s, 2);
    s += __shfl_xor_sync(0xffffffffu, s, 4);
    float ex = expf(s);
    if ((lane & 7) == 0) atomicAdd(&g_DEN1[(long long)dst * H1n + (lane >> 3)], ex);
    float* op = g_ACC1 + (long long)dst * HCc + lane * 8;
    #pragma unroll
    for (int j = 0; j < 8; j++) atomicAdd(op + j, ex * xlv[j]);
}

// ------------- node epilogue: softmax-div + skip + LN + ELU + conv2 proj --
__device__ __forceinline__ float block_sum_256(float v, float* red) {
    int t = threadIdx.x;
    red[t] = v;
    __syncthreads();
    #pragma unroll
    for (int s = 128; s > 0; s >>= 1) {
        if (t < s) red[t] += red[t + s];
        __syncthreads();
    }
    float r = red[0];
    __syncthreads();
    return r;
}

__global__ __launch_bounds__(256) void node_kernel(
    const float* __restrict__ bias1,
    const float* __restrict__ gamma, const float* __restrict__ beta,
    const float* __restrict__ W2l, const float* __restrict__ b2l,
    const float* __restrict__ W2r, const float* __restrict__ b2r,
    const float* __restrict__ att2)
{
    __shared__ float red[256];
    const int n = blockIdx.x;
    const int c = threadIdx.x;
    float v = g_ACC1[(long long)n * HCc + c] / g_DEN1[n * H1n + (c >> 6)]
              + bias1[c] + g_SKIP[(long long)n * HCc + c];
    float mu = block_sum_256(v, red) * (1.0f / 256.0f);
    float d = v - mu;
    float var = block_sum_256(d * d, red) * (1.0f / 256.0f);
    float h = d * rsqrtf(var + 1e-5f) * gamma[c] + beta[c];
    h = h > 0.f ? h : expm1f(h);   // ELU (alpha=1), eval-mode dropout = id
    float s0 = block_sum_256(h * W2l[c * 2 + 0], red);
    float s1 = block_sum_256(h * W2l[c * 2 + 1], red);
    float s2 = block_sum_256(h * W2r[c * 2 + 0], red);
    float s3 = block_sum_256(h * W2r[c * 2 + 1], red);
    if (c == 0) {
        float xl0 = s0 + b2l[0], xl1 = s1 + b2l[1];
        float xr0 = s2 + b2r[0], xr1 = s3 + b2r[1];
        g_XL2[n * 2 + 0] = xl0; g_XL2[n * 2 + 1] = xl1;
        g_XR2[n * 2 + 0] = xr0; g_XR2[n * 2 + 1] = xr1;
        float e0 = xl0 + xr0; e0 = e0 > 0.f ? e0 : NEG * e0;
        float e1 = xl1 + xr1; e1 = e1 > 0.f ? e1 : NEG * e1;
        float ex = expf(e0 * att2[0] + e1 * att2[1]);
        g_DEN2[n] = ex;                      // self-loop contribution
        g_ACC2[n * 2 + 0] = ex * xl0;
        g_ACC2[n * 2 + 1] = ex * xl1;
    }
}

// ------------- conv2 edge pass (thread / edge) ----------------------------
__global__ void conv2_edge_kernel(const void* __restrict__ ei,
                                  const float* __restrict__ att2,
                                  long long E) {
    long long e = (long long)blockIdx.x * blockDim.x + threadIdx.x;
    if (e >= E) return;
    int is64 = g_is64;
    int src = ld_idx(ei, e, is64);
    int dst = ld_idx(ei, E + e, is64);
    float xl0 = g_XL2[src * 2 + 0], xl1 = g_XL2[src * 2 + 1];
    float xr0 = g_XR2[dst * 2 + 0], xr1 = g_XR2[dst * 2 + 1];
    float e0 = xl0 + xr0; e0 = e0 > 0.f ? e0 : NEG * e0;
    float e1 = xl1 + xr1; e1 = e1 > 0.f ? e1 : NEG * e1;
    float ex = expf(e0 * att2[0] + e1 * att2[1]);
    atomicAdd(&g_DEN2[dst], ex);
    atomicAdd(&g_ACC2[dst * 2 + 0], ex * xl0);
    atomicAdd(&g_ACC2[dst * 2 + 1], ex * xl1);
}

// ------------- final: normalize + bias2 -----------------------------------
__global__ void final_kernel(const float* __restrict__ bias2,
                             float* __restrict__ out, int N) {
    int i = blockIdx.x * blockDim.x + threadIdx.x;
    if (i >= N) return;
    float dinv = 1.0f / g_DEN2[i];
    out[i * 2 + 0] = g_ACC2[i * 2 + 0] * dinv + bias2[0];
    out[i * 2 + 1] = g_ACC2[i * 2 + 1] * dinv + bias2[1];
}

// ---------------------------------------------------------------------------
extern "C" void kernel_launch(void* const* d_in, const int* in_sizes, int n_in,
                              void* d_out, int out_size) {
    const float* x     = (const float*)d_in[0];
    const void*  ei    = d_in[1];
    const float* W1l   = (const float*)d_in[2];
    const float* b1l   = (const float*)d_in[3];
    const float* W1r   = (const float*)d_in[4];
    const float* b1r   = (const float*)d_in[5];
    const float* att1  = (const float*)d_in[6];
    const float* bias1 = (const float*)d_in[7];
    const float* W2l   = (const float*)d_in[8];
    const float* b2l   = (const float*)d_in[9];
    const float* W2r   = (const float*)d_in[10];
    const float* b2r   = (const float*)d_in[11];
    const float* att2  = (const float*)d_in[12];
    const float* bias2 = (const float*)d_in[13];
    const float* Wskip = (const float*)d_in[14];
    const float* bskip = (const float*)d_in[15];
    const float* gamma = (const float*)d_in[16];
    const float* beta  = (const float*)d_in[17];
    float* out = (float*)d_out;

    const int       N = in_sizes[0] / DIN;     // 50000
    const long long E = (long long)in_sizes[1] / 2;  // 800000

    // device pointers for scratch (kernels use the globals directly)
    float *dXL1, *dXR1, *dSKIP;
    cudaGetSymbolAddress((void**)&dXL1, g_XL1);
    cudaGetSymbolAddress((void**)&dXR1, g_XR1);
    cudaGetSymbolAddress((void**)&dSKIP, g_SKIP);

    detect_idx_kernel<<<1, 1>>>((const unsigned int*)ei);

    dim3 gg((HCc + BN - 1) / BN, (N + BM - 1) / BM);
    sgemm_bias_kernel<<<gg, 256>>>(x, W1l, b1l, dXL1, N, HCc, DIN);
    sgemm_bias_kernel<<<gg, 256>>>(x, W1r, b1r, dXR1, N, HCc, DIN);
    sgemm_bias_kernel<<<gg, 256>>>(x, Wskip, bskip, dSKIP, N, HCc, DIN);

    // self loops init acc/den for every node (non-atomic)
    {
        long long warps = N;
        int blocks = (int)((warps + 7) / 8);
        conv1_selfloop_kernel<<<blocks, 256>>>(att1, N);
    }
    // conv1 edge pass
    {
        int blocks = (int)((E + 7) / 8);
        conv1_edge_kernel<<<blocks, 256>>>(ei, att1, E);
    }
    // node epilogue: softmax div + skip + LN + ELU + conv2 projections + self loop 2
    node_kernel<<<N, 256>>>(bias1, gamma, beta, W2l, b2l, W2r, b2r, att2);
    // conv2 edge pass
    {
        int blocks = (int)((E + 255) / 256);
        conv2_edge_kernel<<<blocks, 256>>>(ei, att2, E);
    }
    // final output
    final_kernel<<<(N + 255) / 256, 256>>>(bias2, out, N);
}

// round 2
// speedup vs baseline: 1.8431x; 1.8431x over previous
#include <cuda_runtime.h>
#include <math.h>

// Problem constants (fixed by the reference)
#define DIN   256     // input feature dim
#define HCc   256     // H1*C1 = hidden dim
#define H1n   4
#define C1n   64
#define NEG   0.2f
#define MAXN  50000

// ---------------- scratch (static device globals: allowed) ----------------
__device__ float g_XL1[(long long)MAXN * HCc];   // x @ W1l + b1l
__device__ float g_XR1[(long long)MAXN * HCc];   // x @ W1r + b1r
__device__ float g_SKIP[(long long)MAXN * HCc];  // x @ Wskip + bskip
__device__ float g_ACC1[(long long)MAXN * HCc];  // sum_e exp(l)*xl[src]
__device__ float g_DEN1[MAXN * H1n];             // sum_e exp(l)
__device__ float g_XL2[MAXN * 2];
__device__ float g_XR2[MAXN * 2];
__device__ float g_ACC2[MAXN * 2];
__device__ float g_DEN2[MAXN];
__device__ int   g_is64;

// ---------------- dtype detection for edge_index (int32 vs int64) --------
__global__ void detect_idx_kernel(const unsigned int* __restrict__ w) {
    int ok = 1;
    #pragma unroll
    for (int i = 0; i < 32; i++) {
        if (w[2 * i + 1] != 0u) { ok = 0; break; }
    }
    g_is64 = ok;
}

__device__ __forceinline__ int ld_idx(const void* ei, long long pos, int is64) {
    if (is64) return (int)(((const long long*)ei)[pos]);
    return ((const int*)ei)[pos];
}

// ---------------- fused triple SGEMM: C[sel] = A @ B[sel] + bias[sel] ------
// 128x128x16 tiles, 256 threads, 8x8 acc/thread, double-buffered smem.
#define TM 128
#define TN 128
#define TK 16

__global__ __launch_bounds__(256) void sgemm3_kernel(
    const float* __restrict__ A,
    const float* __restrict__ B0, const float* __restrict__ B1,
    const float* __restrict__ B2,
    const float* __restrict__ bias0, const float* __restrict__ bias1,
    const float* __restrict__ bias2,
    float* __restrict__ C0, float* __restrict__ C1, float* __restrict__ C2,
    int M, int K)   // Nc fixed = 256
{
    const int sel = blockIdx.x >> 1;
    const int n0  = (blockIdx.x & 1) * TN;
    const float* B    = (sel == 0) ? B0 : (sel == 1) ? B1 : B2;
    const float* bias = (sel == 0) ? bias0 : (sel == 1) ? bias1 : bias2;
    float*       C    = (sel == 0) ? C0 : (sel == 1) ? C1 : C2;
    const int m0 = blockIdx.y * TM;

    __shared__ float As[2][TK][TM];
    __shared__ float Bs[2][TK][TN];

    const int tid = threadIdx.x;
    const int tm  = tid >> 4;   // 0..15 -> rows tm*8..tm*8+7
    const int tn  = tid & 15;   // 0..15 -> cols tn*8..tn*8+7

    // A-tile load map: 128 rows x 16 k = 512 float4; 2 per thread
    const int ar0 = tid >> 2;            // 0..63
    const int akq = (tid & 3) * 4;       // 0,4,8,12
    // B-tile load map: 16 k-rows x 128 cols = 512 float4; 2 per thread
    const int br0 = tid >> 5;            // 0..7
    const int bcq = (tid & 31) * 4;      // 0..124

    float acc[8][8];
    #pragma unroll
    for (int i = 0; i < 8; i++)
        #pragma unroll
        for (int j = 0; j < 8; j++) acc[i][j] = 0.f;

    float4 ra[2], rb[2];

    // prologue: load tile 0 directly to smem buf 0
    #pragma unroll
    for (int it = 0; it < 2; it++) {
        int row = ar0 + it * 64;
        float4 v = make_float4(0.f, 0.f, 0.f, 0.f);
        if (m0 + row < M)
            v = *(const float4*)(A + (long long)(m0 + row) * K + akq);
        As[0][akq + 0][row] = v.x; As[0][akq + 1][row] = v.y;
        As[0][akq + 2][row] = v.z; As[0][akq + 3][row] = v.w;
        int krow = br0 + it * 8;
        float4 w = *(const float4*)(B + (long long)krow * 256 + n0 + bcq);
        *(float4*)&Bs[0][krow][bcq] = w;
    }
    __syncthreads();

    int buf = 0;
    for (int k0 = 0; k0 < K; k0 += TK) {
        const int kn = k0 + TK;
        if (kn < K) {
            #pragma unroll
            for (int it = 0; it < 2; it++) {
                int row = ar0 + it * 64;
                ra[it] = make_float4(0.f, 0.f, 0.f, 0.f);
                if (m0 + row < M)
                    ra[it] = *(const float4*)(A + (long long)(m0 + row) * K + kn + akq);
                int krow = br0 + it * 8;
                rb[it] = *(const float4*)(B + (long long)(kn + krow) * 256 + n0 + bcq);
            }
        }
        #pragma unroll
        for (int k = 0; k < TK; k++) {
            float4 a0 = *(const float4*)&As[buf][k][tm * 8];
            float4 a1 = *(const float4*)&As[buf][k][tm * 8 + 4];
            float4 b0 = *(const float4*)&Bs[buf][k][tn * 8];
            float4 b1 = *(const float4*)&Bs[buf][k][tn * 8 + 4];
            float av[8] = {a0.x, a0.y, a0.z, a0.w, a1.x, a1.y, a1.z, a1.w};
            float bv[8] = {b0.x, b0.y, b0.z, b0.w, b1.x, b1.y, b1.z, b1.w};
            #pragma unroll
            for (int i = 0; i < 8; i++)
                #pragma unroll
                for (int j = 0; j < 8; j++)
                    acc[i][j] = fmaf(av[i], bv[j], acc[i][j]);
        }
        if (kn < K) {
            int nb = buf ^ 1;
            #pragma unroll
            for (int it = 0; it < 2; it++) {
                int row = ar0 + it * 64;
                As[nb][akq + 0][row] = ra[it].x; As[nb][akq + 1][row] = ra[it].y;
                As[nb][akq + 2][row] = ra[it].z; As[nb][akq + 3][row] = ra[it].w;
                int krow = br0 + it * 8;
                *(float4*)&Bs[nb][krow][bcq] = rb[it];
            }
        }
        __syncthreads();
        buf ^= 1;
    }

    const int c0 = n0 + tn * 8;
    float4 bv0 = *(const float4*)(bias + c0);
    float4 bv1 = *(const float4*)(bias + c0 + 4);
    float bb[8] = {bv0.x, bv0.y, bv0.z, bv0.w, bv1.x, bv1.y, bv1.z, bv1.w};
    #pragma unroll
    for (int i = 0; i < 8; i++) {
        int m = m0 + tm * 8 + i;
        if (m < M) {
            float4 o0, o1;
            o0.x = acc[i][0] + bb[0]; o0.y = acc[i][1] + bb[1];
            o0.z = acc[i][2] + bb[2]; o0.w = acc[i][3] + bb[3];
            o1.x = acc[i][4] + bb[4]; o1.y = acc[i][5] + bb[5];
            o1.z = acc[i][6] + bb[6]; o1.w = acc[i][7] + bb[7];
            *(float4*)(C + (long long)m * 256 + c0) = o0;
            *(float4*)(C + (long long)m * 256 + c0 + 4) = o1;
        }
    }
}

// ------------- conv1 self-loop init (non-atomic; one warp / node) --------
__global__ void conv1_selfloop_kernel(const float* __restrict__ att1, int N) {
    long long wid = ((long long)blockIdx.x * blockDim.x + threadIdx.x) >> 5;
    int lane = threadIdx.x & 31;
    if (wid >= N) return;
    const float* xl = g_XL1 + wid * HCc;
    const float* xr = g_XR1 + wid * HCc;
    float4 xl0 = *(const float4*)(xl + lane * 8);
    float4 xl1 = *(const float4*)(xl + lane * 8 + 4);
    float4 xr0 = *(const float4*)(xr + lane * 8);
    float4 xr1 = *(const float4*)(xr + lane * 8 + 4);
    float xlv[8] = {xl0.x, xl0.y, xl0.z, xl0.w, xl1.x, xl1.y, xl1.z, xl1.w};
    float xrv[8] = {xr0.x, xr0.y, xr0.z, xr0.w, xr1.x, xr1.y, xr1.z, xr1.w};
    float s = 0.f;
    #pragma unroll
    for (int j = 0; j < 8; j++) {
        float e = xlv[j] + xrv[j];
        e = e > 0.f ? e : NEG * e;
        s += e * att1[lane * 8 + j];
    }
    s += __shfl_xor_sync(0xffffffffu, s, 1);
    s += __shfl_xor_sync(0xffffffffu, s, 2);
    s += __shfl_xor_sync(0xffffffffu, s, 4);
    float ex = expf(s);
    if ((lane & 7) == 0) g_DEN1[wid * H1n + (lane >> 3)] = ex;
    float* op = g_ACC1 + wid * HCc + lane * 8;
    float4 o0, o1;
    o0.x = ex * xlv[0]; o0.y = ex * xlv[1]; o0.z = ex * xlv[2]; o0.w = ex * xlv[3];
    o1.x = ex * xlv[4]; o1.y = ex * xlv[5]; o1.z = ex * xlv[6]; o1.w = ex * xlv[7];
    *(float4*)(op) = o0;
    *(float4*)(op + 4) = o1;
}

// ------------- conv1 edge pass (one warp / edge, vector red) --------------
__device__ __forceinline__ void red_add_v4(float* p, float a, float b, float c, float d) {
    asm volatile("red.global.add.v4.f32 [%0], {%1, %2, %3, %4};"
                 :: "l"(p), "f"(a), "f"(b), "f"(c), "f"(d) : "memory");
}
__device__ __forceinline__ void red_add_v2(float* p, float a, float b) {
    asm volatile("red.global.add.v2.f32 [%0], {%1, %2};"
                 :: "l"(p), "f"(a), "f"(b) : "memory");
}

__global__ void conv1_edge_kernel(const void* __restrict__ ei,
                                  const float* __restrict__ att1,
                                  long long E) {
    long long wid = ((long long)blockIdx.x * blockDim.x + threadIdx.x) >> 5;
    int lane = threadIdx.x & 31;
    if (wid >= E) return;
    int is64 = g_is64;
    int src = ld_idx(ei, wid, is64);
    int dst = ld_idx(ei, E + wid, is64);
    const float* xl = g_XL1 + (long long)src * HCc;
    const float* xr = g_XR1 + (long long)dst * HCc;
    float4 xl0 = *(const float4*)(xl + lane * 8);
    float4 xl1 = *(const float4*)(xl + lane * 8 + 4);
    float4 xr0 = *(const float4*)(xr + lane * 8);
    float4 xr1 = *(const float4*)(xr + lane * 8 + 4);
    float xlv[8] = {xl0.x, xl0.y, xl0.z, xl0.w, xl1.x, xl1.y, xl1.z, xl1.w};
    float xrv[8] = {xr0.x, xr0.y, xr0.z, xr0.w, xr1.x, xr1.y, xr1.z, xr1.w};
    float s = 0.f;
    #pragma unroll
    for (int j = 0; j < 8; j++) {
        float e = xlv[j] + xrv[j];
        e = e > 0.f ? e : NEG * e;
        s += e * att1[lane * 8 + j];
    }
    s += __shfl_xor_sync(0xffffffffu, s, 1);
    s += __shfl_xor_sync(0xffffffffu, s, 2);
    s += __shfl_xor_sync(0xffffffffu, s, 4);
    float ex = expf(s);
    if ((lane & 7) == 0) atomicAdd(&g_DEN1[(long long)dst * H1n + (lane >> 3)], ex);
    float* op = g_ACC1 + (long long)dst * HCc + lane * 8;
    red_add_v4(op,     ex * xlv[0], ex * xlv[1], ex * xlv[2], ex * xlv[3]);
    red_add_v4(op + 4, ex * xlv[4], ex * xlv[5], ex * xlv[6], ex * xlv[7]);
}

// ------------- node epilogue: softmax-div + skip + LN + ELU + conv2 proj --
__global__ __launch_bounds__(256) void node_kernel(
    const float* __restrict__ bias1,
    const float* __restrict__ gamma, const float* __restrict__ beta,
    const float* __restrict__ W2l, const float* __restrict__ b2l,
    const float* __restrict__ W2r, const float* __restrict__ b2r,
    const float* __restrict__ att2)
{
    __shared__ float sred[4][8];
    const int n = blockIdx.x;
    const int c = threadIdx.x;
    const int lane = c & 31;
    const int warp = c >> 5;

    float v = g_ACC1[(long long)n * HCc + c] / g_DEN1[n * H1n + (c >> 6)]
              + bias1[c] + g_SKIP[(long long)n * HCc + c];

    // mean
    float t = v;
    #pragma unroll
    for (int o = 16; o > 0; o >>= 1) t += __shfl_xor_sync(0xffffffffu, t, o);
    if (lane == 0) sred[0][warp] = t;
    __syncthreads();
    float mu = 0.f;
    #pragma unroll
    for (int i = 0; i < 8; i++) mu += sred[0][i];
    mu *= (1.0f / 256.0f);
    __syncthreads();

    // var
    float d = v - mu;
    t = d * d;
    #pragma unroll
    for (int o = 16; o > 0; o >>= 1) t += __shfl_xor_sync(0xffffffffu, t, o);
    if (lane == 0) sred[0][warp] = t;
    __syncthreads();
    float var = 0.f;
    #pragma unroll
    for (int i = 0; i < 8; i++) var += sred[0][i];
    var *= (1.0f / 256.0f);
    __syncthreads();

    float h = d * rsqrtf(var + 1e-5f) * gamma[c] + beta[c];
    h = h > 0.f ? h : expm1f(h);   // ELU (alpha=1)

    // four projections in one round
    float p0 = h * W2l[c * 2 + 0];
    float p1 = h * W2l[c * 2 + 1];
    float p2 = h * W2r[c * 2 + 0];
    float p3 = h * W2r[c * 2 + 1];
    #pragma unroll
    for (int o = 16; o > 0; o >>= 1) {
        p0 += __shfl_xor_sync(0xffffffffu, p0, o);
        p1 += __shfl_xor_sync(0xffffffffu, p1, o);
        p2 += __shfl_xor_sync(0xffffffffu, p2, o);
        p3 += __shfl_xor_sync(0xffffffffu, p3, o);
    }
    if (lane == 0) {
        sred[0][warp] = p0; sred[1][warp] = p1;
        sred[2][warp] = p2; sred[3][warp] = p3;
    }
    __syncthreads();
    if (c == 0) {
        float s0 = 0.f, s1 = 0.f, s2 = 0.f, s3 = 0.f;
        #pragma unroll
        for (int i = 0; i < 8; i++) {
            s0 += sred[0][i]; s1 += sred[1][i];
            s2 += sred[2][i]; s3 += sred[3][i];
        }
        float xl0 = s0 + b2l[0], xl1 = s1 + b2l[1];
        float xr0 = s2 + b2r[0], xr1 = s3 + b2r[1];
        g_XL2[n * 2 + 0] = xl0; g_XL2[n * 2 + 1] = xl1;
        g_XR2[n * 2 + 0] = xr0; g_XR2[n * 2 + 1] = xr1;
        float e0 = xl0 + xr0; e0 = e0 > 0.f ? e0 : NEG * e0;
        float e1 = xl1 + xr1; e1 = e1 > 0.f ? e1 : NEG * e1;
        float ex = expf(e0 * att2[0] + e1 * att2[1]);
        g_DEN2[n] = ex;                      // self-loop contribution
        g_ACC2[n * 2 + 0] = ex * xl0;
        g_ACC2[n * 2 + 1] = ex * xl1;
    }
}

// ------------- conv2 edge pass (thread / edge) ----------------------------
__global__ void conv2_edge_kernel(const void* __restrict__ ei,
                                  const float* __restrict__ att2,
                                  long long E) {
    long long e = (long long)blockIdx.x * blockDim.x + threadIdx.x;
    if (e >= E) return;
    int is64 = g_is64;
    int src = ld_idx(ei, e, is64);
    int dst = ld_idx(ei, E + e, is64);
    float xl0 = g_XL2[src * 2 + 0], xl1 = g_XL2[src * 2 + 1];
    float xr0 = g_XR2[dst * 2 + 0], xr1 = g_XR2[dst * 2 + 1];
    float e0 = xl0 + xr0; e0 = e0 > 0.f ? e0 : NEG * e0;
    float e1 = xl1 + xr1; e1 = e1 > 0.f ? e1 : NEG * e1;
    float ex = expf(e0 * att2[0] + e1 * att2[1]);
    atomicAdd(&g_DEN2[dst], ex);
    red_add_v2(&g_ACC2[dst * 2], ex * xl0, ex * xl1);
}

// ------------- final: normalize + bias2 -----------------------------------
__global__ void final_kernel(const float* __restrict__ bias2,
                             float* __restrict__ out, int N) {
    int i = blockIdx.x * blockDim.x + threadIdx.x;
    if (i >= N) return;
    float dinv = 1.0f / g_DEN2[i];
    float2 o;
    o.x = g_ACC2[i * 2 + 0] * dinv + bias2[0];
    o.y = g_ACC2[i * 2 + 1] * dinv + bias2[1];
    *(float2*)(out + i * 2) = o;
}

// ---------------------------------------------------------------------------
extern "C" void kernel_launch(void* const* d_in, const int* in_sizes, int n_in,
                              void* d_out, int out_size) {
    const float* x     = (const float*)d_in[0];
    const void*  ei    = d_in[1];
    const float* W1l   = (const float*)d_in[2];
    const float* b1l   = (const float*)d_in[3];
    const float* W1r   = (const float*)d_in[4];
    const float* b1r   = (const float*)d_in[5];
    const float* att1  = (const float*)d_in[6];
    const float* bias1 = (const float*)d_in[7];
    const float* W2l   = (const float*)d_in[8];
    const float* b2l   = (const float*)d_in[9];
    const float* W2r   = (const float*)d_in[10];
    const float* b2r   = (const float*)d_in[11];
    const float* att2  = (const float*)d_in[12];
    const float* bias2 = (const float*)d_in[13];
    const float* Wskip = (const float*)d_in[14];
    const float* bskip = (const float*)d_in[15];
    const float* gamma = (const float*)d_in[16];
    const float* beta  = (const float*)d_in[17];
    float* out = (float*)d_out;

    const int       N = in_sizes[0] / DIN;            // 50000
    const long long E = (long long)in_sizes[1] / 2;   // 800000

    float *dXL1, *dXR1, *dSKIP;
    cudaGetSymbolAddress((void**)&dXL1, g_XL1);
    cudaGetSymbolAddress((void**)&dXR1, g_XR1);
    cudaGetSymbolAddress((void**)&dSKIP, g_SKIP);

    detect_idx_kernel<<<1, 1>>>((const unsigned int*)ei);

    // fused triple GEMM: blockIdx.x in [0,6) = {W1l, W1r, Wskip} x {n0=0,128}
    dim3 gg(6, (N + TM - 1) / TM);
    sgemm3_kernel<<<gg, 256>>>(x, W1l, W1r, Wskip, b1l, b1r, bskip,
                               dXL1, dXR1, dSKIP, N, DIN);

    // self loops init acc/den for every node (non-atomic)
    conv1_selfloop_kernel<<<(N + 7) / 8, 256>>>(att1, N);

    // conv1 edge pass (one warp / edge, vector red)
    conv1_edge_kernel<<<(int)((E + 7) / 8), 256>>>(ei, att1, E);

    // node epilogue
    node_kernel<<<N, 256>>>(bias1, gamma, beta, W2l, b2l, W2r, b2r, att2);

    // conv2 edge pass
    conv2_edge_kernel<<<(int)((E + 255) / 256), 256>>>(ei, att2, E);

    // final output
    final_kernel<<<(N + 255) / 256, 256>>>(bias2, out, N);
}

// round 3
// speedup vs baseline: 2.7552x; 1.4948x over previous
#include <cuda_runtime.h>
#include <math.h>

// Problem constants (fixed by the reference)
#define DIN   256
#define HCc   256
#define H1n   4
#define NEG   0.2f
#define MAXN  50000
#define MAXE  1000000

// ---------------- scratch (static device globals) --------------------------
__device__ float g_XL1[(long long)MAXN * HCc];
__device__ float g_XR1[(long long)MAXN * HCc];
__device__ float g_SKIP[(long long)MAXN * HCc];
__device__ float g_XL2[MAXN * 2];
__device__ float g_XR2[MAXN * 2];
__device__ int   g_deg[MAXN];
__device__ int   g_rowptr[MAXN + 1];
__device__ int   g_cur[MAXN];
__device__ int   g_esrc[MAXE];
__device__ int   g_is64;

// ---------------- dtype detection for edge_index (int32 vs int64) ---------
__global__ void detect_idx_kernel(const unsigned int* __restrict__ w) {
    int ok = 1;
    #pragma unroll
    for (int i = 0; i < 32; i++) {
        if (w[2 * i + 1] != 0u) { ok = 0; break; }
    }
    g_is64 = ok;
}

__device__ __forceinline__ int ld_idx(const void* ei, long long pos, int is64) {
    if (is64) return (int)(((const long long*)ei)[pos]);
    return ((const int*)ei)[pos];
}

// ---------------- CSR build -------------------------------------------------
__global__ void zero_deg_kernel(int N) {
    int i = blockIdx.x * blockDim.x + threadIdx.x;
    if (i < N) g_deg[i] = 0;
}

__global__ void hist_kernel(const void* __restrict__ ei, long long E) {
    long long e = (long long)blockIdx.x * blockDim.x + threadIdx.x;
    if (e >= E) return;
    int dst = ld_idx(ei, E + e, g_is64);
    atomicAdd(&g_deg[dst], 1);
}

// single-block scan over N (<=50000); writes rowptr (exclusive->[i+1]) and cur
__global__ __launch_bounds__(1024) void scan_kernel(int N) {
    __shared__ int warp_sums[32];
    __shared__ int s_carry;
    const int lane = threadIdx.x & 31;
    const int warp = threadIdx.x >> 5;
    if (threadIdx.x == 0) { s_carry = 0; g_rowptr[0] = 0; }
    __syncthreads();
    for (int base = 0; base < N; base += 1024) {
        int i = base + threadIdx.x;
        int v = (i < N) ? g_deg[i] : 0;
        int x = v;
        #pragma unroll
        for (int o = 1; o < 32; o <<= 1) {
            int y = __shfl_up_sync(0xffffffffu, x, o);
            if (lane >= o) x += y;
        }
        if (lane == 31) warp_sums[warp] = x;
        __syncthreads();
        if (warp == 0) {
            int w = warp_sums[lane];
            #pragma unroll
            for (int o = 1; o < 32; o <<= 1) {
                int y = __shfl_up_sync(0xffffffffu, w, o);
                if (lane >= o) w += y;
            }
            warp_sums[lane] = w;
        }
        __syncthreads();
        int incl = x + (warp > 0 ? warp_sums[warp - 1] : 0) + s_carry;
        if (i < N) { g_rowptr[i + 1] = incl; g_cur[i] = incl - v; }
        __syncthreads();
        if (threadIdx.x == 1023) s_carry = incl;
        __syncthreads();
    }
}

__global__ void scatter_kernel(const void* __restrict__ ei, long long E) {
    long long e = (long long)blockIdx.x * blockDim.x + threadIdx.x;
    if (e >= E) return;
    int is64 = g_is64;
    int src = ld_idx(ei, e, is64);
    int dst = ld_idx(ei, E + e, is64);
    int pos = atomicAdd(&g_cur[dst], 1);
    g_esrc[pos] = src;
}

// ---------------- fused triple SGEMM (unchanged from R2) -------------------
#define TM 128
#define TN 128
#define TK 16

__global__ __launch_bounds__(256) void sgemm3_kernel(
    const float* __restrict__ A,
    const float* __restrict__ B0, const float* __restrict__ B1,
    const float* __restrict__ B2,
    const float* __restrict__ bias0, const float* __restrict__ bias1,
    const float* __restrict__ bias2,
    float* __restrict__ C0, float* __restrict__ C1, float* __restrict__ C2,
    int M, int K)
{
    const int sel = blockIdx.x >> 1;
    const int n0  = (blockIdx.x & 1) * TN;
    const float* B    = (sel == 0) ? B0 : (sel == 1) ? B1 : B2;
    const float* bias = (sel == 0) ? bias0 : (sel == 1) ? bias1 : bias2;
    float*       C    = (sel == 0) ? C0 : (sel == 1) ? C1 : C2;
    const int m0 = blockIdx.y * TM;

    __shared__ float As[2][TK][TM];
    __shared__ float Bs[2][TK][TN];

    const int tid = threadIdx.x;
    const int tm  = tid >> 4;
    const int tn  = tid & 15;
    const int ar0 = tid >> 2;
    const int akq = (tid & 3) * 4;
    const int br0 = tid >> 5;
    const int bcq = (tid & 31) * 4;

    float acc[8][8];
    #pragma unroll
    for (int i = 0; i < 8; i++)
        #pragma unroll
        for (int j = 0; j < 8; j++) acc[i][j] = 0.f;

    float4 ra[2], rb[2];

    #pragma unroll
    for (int it = 0; it < 2; it++) {
        int row = ar0 + it * 64;
        float4 v = make_float4(0.f, 0.f, 0.f, 0.f);
        if (m0 + row < M)
            v = *(const float4*)(A + (long long)(m0 + row) * K + akq);
        As[0][akq + 0][row] = v.x; As[0][akq + 1][row] = v.y;
        As[0][akq + 2][row] = v.z; As[0][akq + 3][row] = v.w;
        int krow = br0 + it * 8;
        float4 w = *(const float4*)(B + (long long)krow * 256 + n0 + bcq);
        *(float4*)&Bs[0][krow][bcq] = w;
    }
    __syncthreads();

    int buf = 0;
    for (int k0 = 0; k0 < K; k0 += TK) {
        const int kn = k0 + TK;
        if (kn < K) {
            #pragma unroll
            for (int it = 0; it < 2; it++) {
                int row = ar0 + it * 64;
                ra[it] = make_float4(0.f, 0.f, 0.f, 0.f);
                if (m0 + row < M)
                    ra[it] = *(const float4*)(A + (long long)(m0 + row) * K + kn + akq);
                int krow = br0 + it * 8;
                rb[it] = *(const float4*)(B + (long long)(kn + krow) * 256 + n0 + bcq);
            }
        }
        #pragma unroll
        for (int k = 0; k < TK; k++) {
            float4 a0 = *(const float4*)&As[buf][k][tm * 8];
            float4 a1 = *(const float4*)&As[buf][k][tm * 8 + 4];
            float4 b0 = *(const float4*)&Bs[buf][k][tn * 8];
            float4 b1 = *(const float4*)&Bs[buf][k][tn * 8 + 4];
            float av[8] = {a0.x, a0.y, a0.z, a0.w, a1.x, a1.y, a1.z, a1.w};
            float bv[8] = {b0.x, b0.y, b0.z, b0.w, b1.x, b1.y, b1.z, b1.w};
            #pragma unroll
            for (int i = 0; i < 8; i++)
                #pragma unroll
                for (int j = 0; j < 8; j++)
                    acc[i][j] = fmaf(av[i], bv[j], acc[i][j]);
        }
        if (kn < K) {
            int nb = buf ^ 1;
            #pragma unroll
            for (int it = 0; it < 2; it++) {
                int row = ar0 + it * 64;
                As[nb][akq + 0][row] = ra[it].x; As[nb][akq + 1][row] = ra[it].y;
                As[nb][akq + 2][row] = ra[it].z; As[nb][akq + 3][row] = ra[it].w;
                int krow = br0 + it * 8;
                *(float4*)&Bs[nb][krow][bcq] = rb[it];
            }
        }
        __syncthreads();
        buf ^= 1;
    }

    const int c0 = n0 + tn * 8;
    float4 bv0 = *(const float4*)(bias + c0);
    float4 bv1 = *(const float4*)(bias + c0 + 4);
    float bb[8] = {bv0.x, bv0.y, bv0.z, bv0.w, bv1.x, bv1.y, bv1.z, bv1.w};
    #pragma unroll
    for (int i = 0; i < 8; i++) {
        int m = m0 + tm * 8 + i;
        if (m < M) {
            float4 o0, o1;
            o0.x = acc[i][0] + bb[0]; o0.y = acc[i][1] + bb[1];
            o0.z = acc[i][2] + bb[2]; o0.w = acc[i][3] + bb[3];
            o1.x = acc[i][4] + bb[4]; o1.y = acc[i][5] + bb[5];
            o1.z = acc[i][6] + bb[6]; o1.w = acc[i][7] + bb[7];
            *(float4*)(C + (long long)m * 256 + c0) = o0;
            *(float4*)(C + (long long)m * 256 + c0 + 4) = o1;
        }
    }
}

// ------- fused conv1 CSR + softmax + skip + LN + ELU + conv2 projection ----
// One warp per dst node. Lane owns dims [lane*8, lane*8+8). No atomics.
__global__ __launch_bounds__(256) void conv1_csr_kernel(
    const float* __restrict__ att1, const float* __restrict__ bias1,
    const float* __restrict__ gamma, const float* __restrict__ beta,
    const float* __restrict__ W2l, const float* __restrict__ b2l,
    const float* __restrict__ W2r, const float* __restrict__ b2r,
    const float* __restrict__ att2, int N)
{
    const int n = blockIdx.x * 8 + (threadIdx.x >> 5);
    const int lane = threadIdx.x & 31;
    if (n >= N) return;

    // per-lane constants
    float attv[8];
    {
        float4 a0 = *(const float4*)(att1 + lane * 8);
        float4 a1 = *(const float4*)(att1 + lane * 8 + 4);
        attv[0]=a0.x; attv[1]=a0.y; attv[2]=a0.z; attv[3]=a0.w;
        attv[4]=a1.x; attv[5]=a1.y; attv[6]=a1.z; attv[7]=a1.w;
    }
    float xr[8];
    {
        const float* p = g_XR1 + (long long)n * HCc + lane * 8;
        float4 r0 = *(const float4*)p;
        float4 r1 = *(const float4*)(p + 4);
        xr[0]=r0.x; xr[1]=r0.y; xr[2]=r0.z; xr[3]=r0.w;
        xr[4]=r1.x; xr[5]=r1.y; xr[6]=r1.z; xr[7]=r1.w;
    }

    float acc[8], den;
    // self-loop
    {
        const float* p = g_XL1 + (long long)n * HCc + lane * 8;
        float4 l0 = *(const float4*)p;
        float4 l1 = *(const float4*)(p + 4);
        float xl[8] = {l0.x,l0.y,l0.z,l0.w,l1.x,l1.y,l1.z,l1.w};
        float s = 0.f;
        #pragma unroll
        for (int j = 0; j < 8; j++) {
            float e = xl[j] + xr[j];
            e = e > 0.f ? e : NEG * e;
            s = fmaf(e, attv[j], s);
        }
        s += __shfl_xor_sync(0xffffffffu, s, 1);
        s += __shfl_xor_sync(0xffffffffu, s, 2);
        s += __shfl_xor_sync(0xffffffffu, s, 4);
        float ex = expf(s);
        den = ex;
        #pragma unroll
        for (int j = 0; j < 8; j++) acc[j] = ex * xl[j];
    }

    const int row0 = g_rowptr[n];
    const int row1 = g_rowptr[n + 1];
    int src_next = (row0 < row1) ? g_esrc[row0] : 0;
    for (int i = row0; i < row1; i++) {
        int src = src_next;
        if (i + 1 < row1) src_next = g_esrc[i + 1];
        const float* p = g_XL1 + (long long)src * HCc + lane * 8;
        float4 l0 = *(const float4*)p;
        float4 l1 = *(const float4*)(p + 4);
        float xl[8] = {l0.x,l0.y,l0.z,l0.w,l1.x,l1.y,l1.z,l1.w};
        float s = 0.f;
        #pragma unroll
        for (int j = 0; j < 8; j++) {
            float e = xl[j] + xr[j];
            e = e > 0.f ? e : NEG * e;
            s = fmaf(e, attv[j], s);
        }
        s += __shfl_xor_sync(0xffffffffu, s, 1);
        s += __shfl_xor_sync(0xffffffffu, s, 2);
        s += __shfl_xor_sync(0xffffffffu, s, 4);
        float ex = expf(s);
        den += ex;
        #pragma unroll
        for (int j = 0; j < 8; j++) acc[j] = fmaf(ex, xl[j], acc[j]);
    }

    // softmax divide + bias1 + skip
    const float dinv = 1.0f / den;
    float v[8];
    {
        const float* sp = g_SKIP + (long long)n * HCc + lane * 8;
        float4 s0 = *(const float4*)sp;
        float4 s1 = *(const float4*)(sp + 4);
        float4 b0 = *(const float4*)(bias1 + lane * 8);
        float4 b1 = *(const float4*)(bias1 + lane * 8 + 4);
        float sk[8] = {s0.x,s0.y,s0.z,s0.w,s1.x,s1.y,s1.z,s1.w};
        float bb[8] = {b0.x,b0.y,b0.z,b0.w,b1.x,b1.y,b1.z,b1.w};
        #pragma unroll
        for (int j = 0; j < 8; j++) v[j] = acc[j] * dinv + bb[j] + sk[j];
    }

    // LayerNorm over 256 dims (warp reduction)
    float t = 0.f;
    #pragma unroll
    for (int j = 0; j < 8; j++) t += v[j];
    #pragma unroll
    for (int o = 16; o > 0; o >>= 1) t += __shfl_xor_sync(0xffffffffu, t, o);
    const float mu = t * (1.0f / 256.0f);
    float t2 = 0.f;
    #pragma unroll
    for (int j = 0; j < 8; j++) { float d = v[j] - mu; t2 = fmaf(d, d, t2); }
    #pragma unroll
    for (int o = 16; o > 0; o >>= 1) t2 += __shfl_xor_sync(0xffffffffu, t2, o);
    const float rstd = rsqrtf(t2 * (1.0f / 256.0f) + 1e-5f);

    float h[8];
    {
        float4 g0 = *(const float4*)(gamma + lane * 8);
        float4 g1 = *(const float4*)(gamma + lane * 8 + 4);
        float4 e0 = *(const float4*)(beta + lane * 8);
        float4 e1 = *(const float4*)(beta + lane * 8 + 4);
        float gg[8] = {g0.x,g0.y,g0.z,g0.w,g1.x,g1.y,g1.z,g1.w};
        float be[8] = {e0.x,e0.y,e0.z,e0.w,e1.x,e1.y,e1.z,e1.w};
        #pragma unroll
        for (int j = 0; j < 8; j++) {
            float hh = (v[j] - mu) * rstd * gg[j] + be[j];
            h[j] = hh > 0.f ? hh : expm1f(hh);   // ELU, eval dropout = id
        }
    }

    // conv2 projections: [256]->2 for both l and r
    float p0 = 0.f, p1 = 0.f, p2 = 0.f, p3 = 0.f;
    {
        const float* wl = W2l + lane * 16;   // rows lane*8.., 2 cols interleaved
        const float* wr = W2r + lane * 16;
        float4 wl0 = *(const float4*)wl;
        float4 wl1 = *(const float4*)(wl + 4);
        float4 wl2 = *(const float4*)(wl + 8);
        float4 wl3 = *(const float4*)(wl + 12);
        float4 wr0 = *(const float4*)wr;
        float4 wr1 = *(const float4*)(wr + 4);
        float4 wr2 = *(const float4*)(wr + 8);
        float4 wr3 = *(const float4*)(wr + 12);
        float wlv[16] = {wl0.x,wl0.y,wl0.z,wl0.w, wl1.x,wl1.y,wl1.z,wl1.w,
                         wl2.x,wl2.y,wl2.z,wl2.w, wl3.x,wl3.y,wl3.z,wl3.w};
        float wrv[16] = {wr0.x,wr0.y,wr0.z,wr0.w, wr1.x,wr1.y,wr1.z,wr1.w,
                         wr2.x,wr2.y,wr2.z,wr2.w, wr3.x,wr3.y,wr3.z,wr3.w};
        #pragma unroll
        for (int j = 0; j < 8; j++) {
            p0 = fmaf(h[j], wlv[2 * j + 0], p0);
            p1 = fmaf(h[j], wlv[2 * j + 1], p1);
            p2 = fmaf(h[j], wrv[2 * j + 0], p2);
            p3 = fmaf(h[j], wrv[2 * j + 1], p3);
        }
    }
    #pragma unroll
    for (int o = 16; o > 0; o >>= 1) {
        p0 += __shfl_xor_sync(0xffffffffu, p0, o);
        p1 += __shfl_xor_sync(0xffffffffu, p1, o);
        p2 += __shfl_xor_sync(0xffffffffu, p2, o);
        p3 += __shfl_xor_sync(0xffffffffu, p3, o);
    }
    if (lane == 0) {
        float2 xl2, xr2;
        xl2.x = p0 + b2l[0]; xl2.y = p1 + b2l[1];
        xr2.x = p2 + b2r[0]; xr2.y = p3 + b2r[1];
        *(float2*)&g_XL2[n * 2] = xl2;
        *(float2*)&g_XR2[n * 2] = xr2;
    }
}

// ------------- conv2 CSR + final output (one thread per node) -------------
__global__ void conv2_csr_kernel(const float* __restrict__ att2,
                                 const float* __restrict__ bias2,
                                 float* __restrict__ out, int N) {
    int n = blockIdx.x * blockDim.x + threadIdx.x;
    if (n >= N) return;
    const float a0 = att2[0], a1 = att2[1];
    float2 xls = *(const float2*)&g_XL2[n * 2];
    float2 xr  = *(const float2*)&g_XR2[n * 2];
    // self loop
    float e0 = xls.x + xr.x; e0 = e0 > 0.f ? e0 : NEG * e0;
    float e1 = xls.y + xr.y; e1 = e1 > 0.f ? e1 : NEG * e1;
    float ex = expf(fmaf(e0, a0, e1 * a1));
    float den = ex, s0 = ex * xls.x, s1 = ex * xls.y;
    const int row0 = g_rowptr[n], row1 = g_rowptr[n + 1];
    for (int i = row0; i < row1; i++) {
        int src = g_esrc[i];
        float2 xl = *(const float2*)&g_XL2[src * 2];
        float f0 = xl.x + xr.x; f0 = f0 > 0.f ? f0 : NEG * f0;
        float f1 = xl.y + xr.y; f1 = f1 > 0.f ? f1 : NEG * f1;
        float exi = expf(fmaf(f0, a0, f1 * a1));
        den += exi;
        s0 = fmaf(exi, xl.x, s0);
        s1 = fmaf(exi, xl.y, s1);
    }
    float dinv = 1.0f / den;
    float2 o;
    o.x = s0 * dinv + bias2[0];
    o.y = s1 * dinv + bias2[1];
    *(float2*)(out + n * 2) = o;
}

// ---------------------------------------------------------------------------
extern "C" void kernel_launch(void* const* d_in, const int* in_sizes, int n_in,
                              void* d_out, int out_size) {
    const float* x     = (const float*)d_in[0];
    const void*  ei    = d_in[1];
    const float* W1l   = (const float*)d_in[2];
    const float* b1l   = (const float*)d_in[3];
    const float* W1r   = (const float*)d_in[4];
    const float* b1r   = (const float*)d_in[5];
    const float* att1  = (const float*)d_in[6];
    const float* bias1 = (const float*)d_in[7];
    const float* W2l   = (const float*)d_in[8];
    const float* b2l   = (const float*)d_in[9];
    const float* W2r   = (const float*)d_in[10];
    const float* b2r   = (const float*)d_in[11];
    const float* att2  = (const float*)d_in[12];
    const float* bias2 = (const float*)d_in[13];
    const float* Wskip = (const float*)d_in[14];
    const float* bskip = (const float*)d_in[15];
    const float* gamma = (const float*)d_in[16];
    const float* beta  = (const float*)d_in[17];
    float* out = (float*)d_out;

    const int       N = in_sizes[0] / DIN;            // 50000
    const long long E = (long long)in_sizes[1] / 2;   // 800000

    float *dXL1, *dXR1, *dSKIP;
    cudaGetSymbolAddress((void**)&dXL1, g_XL1);
    cudaGetSymbolAddress((void**)&dXR1, g_XR1);
    cudaGetSymbolAddress((void**)&dSKIP, g_SKIP);

    detect_idx_kernel<<<1, 1>>>((const unsigned int*)ei);

    // CSR build (overlappable with GEMM in-stream order; cheap anyway)
    zero_deg_kernel<<<(N + 255) / 256, 256>>>(N);
    hist_kernel<<<(int)((E + 255) / 256), 256>>>(ei, E);
    scan_kernel<<<1, 1024>>>(N);
    scatter_kernel<<<(int)((E + 255) / 256), 256>>>(ei, E);

    // fused triple GEMM: blockIdx.x in [0,6) = {W1l, W1r, Wskip} x {n0}
    dim3 gg(6, (N + TM - 1) / TM);
    sgemm3_kernel<<<gg, 256>>>(x, W1l, W1r, Wskip, b1l, b1r, bskip,
                               dXL1, dXR1, dSKIP, N, DIN);

    // fused conv1 + epilogue (warp per node, no atomics)
    conv1_csr_kernel<<<(N + 7) / 8, 256>>>(att1, bias1, gamma, beta,
                                           W2l, b2l, W2r, b2r, att2, N);

    // conv2 + final output
    conv2_csr_kernel<<<(N + 255) / 256, 256>>>(att2, bias2, out, N);
}

// round 5
// speedup vs baseline: 3.0526x; 1.1080x over previous
#include <cuda_runtime.h>
#include <math.h>
#include <stdint.h>

// Problem constants
#define DIN   256
#define HCc   256
#define NEG   0.2f
#define MAXN  50000
#define MAXE  1000000

// ---------------- scratch (static device globals) --------------------------
__device__ float g_XL1[(long long)MAXN * HCc];
__device__ float g_XR1[(long long)MAXN * HCc];
__device__ float g_SKIP[(long long)MAXN * HCc];
__device__ float g_XL2[MAXN * 2];
__device__ float g_XR2[MAXN * 2];
__device__ int   g_deg[MAXN];
__device__ int   g_rowptr[MAXN + 1];
__device__ int   g_cur[MAXN];
__device__ int   g_esrc[MAXE];
__device__ int   g_bsum[64];
__device__ int   g_boff[64];
__device__ int   g_is64;

// ---------------- packed f32x2 helpers (Blackwell base-family PTX) ---------
__device__ __forceinline__ unsigned long long f32x2_dup(float a) {
    unsigned long long d;
    asm("mov.b64 %0, {%1, %1};" : "=l"(d) : "r"(__float_as_uint(a)));
    return d;
}
__device__ __forceinline__ unsigned long long f32x2_fma(unsigned long long a,
                                                        unsigned long long b,
                                                        unsigned long long c) {
    unsigned long long d;
    asm("fma.rn.f32x2 %0, %1, %2, %3;" : "=l"(d) : "l"(a), "l"(b), "l"(c));
    return d;
}
__device__ __forceinline__ unsigned long long f32x2_add(unsigned long long a,
                                                        unsigned long long b) {
    unsigned long long d;
    asm("add.rn.f32x2 %0, %1, %2;" : "=l"(d) : "l"(a), "l"(b));
    return d;
}

// ---------------- dtype detection for edge_index (int32 vs int64) ---------
__global__ void detect_idx_kernel(const unsigned int* __restrict__ w) {
    int ok = 1;
    #pragma unroll
    for (int i = 0; i < 32; i++) {
        if (w[2 * i + 1] != 0u) { ok = 0; break; }
    }
    g_is64 = ok;
}
__device__ __forceinline__ int ld_idx(const void* ei, long long pos, int is64) {
    if (is64) return (int)(((const long long*)ei)[pos]);
    return ((const int*)ei)[pos];
}

// ---------------- CSR build -------------------------------------------------
__global__ void zero_deg_kernel(int N) {
    int i = blockIdx.x * blockDim.x + threadIdx.x;
    if (i < N) g_deg[i] = 0;
}
__global__ void hist_kernel(const void* __restrict__ ei, long long E) {
    long long e = (long long)blockIdx.x * blockDim.x + threadIdx.x;
    if (e >= E) return;
    int dst = ld_idx(ei, E + e, g_is64);
    atomicAdd(&g_deg[dst], 1);
}
__global__ __launch_bounds__(1024) void scanA_kernel(int N) {
    __shared__ int wsum[32];
    const int lane = threadIdx.x & 31, warp = threadIdx.x >> 5;
    int i = blockIdx.x * 1024 + threadIdx.x;
    int v = (i < N) ? g_deg[i] : 0;
    int x = v;
    #pragma unroll
    for (int o = 1; o < 32; o <<= 1) {
        int y = __shfl_up_sync(0xffffffffu, x, o);
        if (lane >= o) x += y;
    }
    if (lane == 31) wsum[warp] = x;
    __syncthreads();
    if (warp == 0) {
        int w = wsum[lane];
        #pragma unroll
        for (int o = 1; o < 32; o <<= 1) {
            int y = __shfl_up_sync(0xffffffffu, w, o);
            if (lane >= o) w += y;
        }
        wsum[lane] = w;
    }
    __syncthreads();
    int incl = x + (warp > 0 ? wsum[warp - 1] : 0);
    if (i < N) g_rowptr[i + 1] = incl;
    if (threadIdx.x == 1023) g_bsum[blockIdx.x] = incl;
}
__global__ void scanB_kernel(int B) {
    if (threadIdx.x == 0) {
        int acc = 0;
        for (int b = 0; b < B; b++) { int v = g_bsum[b]; g_boff[b] = acc; acc += v; }
    }
}
__global__ __launch_bounds__(1024) void scanC_kernel(int N) {
    int i = blockIdx.x * 1024 + threadIdx.x;
    if (i == 0) g_rowptr[0] = 0;
    if (i < N) {
        int r = g_rowptr[i + 1] + g_boff[blockIdx.x];
        g_rowptr[i + 1] = r;
        g_cur[i] = r - g_deg[i];
    }
}
__global__ void scatter_kernel(const void* __restrict__ ei, long long E) {
    long long e = (long long)blockIdx.x * blockDim.x + threadIdx.x;
    if (e >= E) return;
    int is64 = g_is64;
    int src = ld_idx(ei, e, is64);
    int dst = ld_idx(ei, E + e, is64);
    int pos = atomicAdd(&g_cur[dst], 1);
    g_esrc[pos] = src;
}

// ---------------- fused triple SGEMM with packed FFMA2 ----------------------
// 128x128x16 tiles, 256 threads, 8x8 acc/thread (as 8x4 f32x2 pairs),
// double-buffered smem. blockIdx.x in [0,6) selects {W1l,W1r,Wskip} x {n-half}.
#define TM 128
#define TN 128
#define TK 16

__global__ __launch_bounds__(256) void sgemm3_kernel(
    const float* __restrict__ A,
    const float* __restrict__ B0, const float* __restrict__ B1,
    const float* __restrict__ B2,
    const float* __restrict__ bias0, const float* __restrict__ bias1,
    const float* __restrict__ bias2,
    float* __restrict__ C0, float* __restrict__ C1, float* __restrict__ C2,
    int M, int K)
{
    const int sel = blockIdx.x >> 1;
    const int n0  = (blockIdx.x & 1) * TN;
    const float* B    = (sel == 0) ? B0 : (sel == 1) ? B1 : B2;
    const float* bias = (sel == 0) ? bias0 : (sel == 1) ? bias1 : bias2;
    float*       C    = (sel == 0) ? C0 : (sel == 1) ? C1 : C2;
    const int m0 = blockIdx.y * TM;

    __shared__ float As[2][TK][TM];
    __shared__ float Bs[2][TK][TN];

    const int tid = threadIdx.x;
    const int tm  = tid >> 4;
    const int tn  = tid & 15;
    const int ar0 = tid >> 2;
    const int akq = (tid & 3) * 4;
    const int br0 = tid >> 5;
    const int bcq = (tid & 31) * 4;

    // accumulators: 8 rows x 4 column-pairs (each pair = 2 fp32)
    unsigned long long acc[8][4];
    #pragma unroll
    for (int i = 0; i < 8; i++)
        #pragma unroll
        for (int j = 0; j < 4; j++) acc[i][j] = 0ull;

    float4 ra[2], rb[2];

    #pragma unroll
    for (int it = 0; it < 2; it++) {
        int row = ar0 + it * 64;
        float4 v = make_float4(0.f, 0.f, 0.f, 0.f);
        if (m0 + row < M)
            v = *(const float4*)(A + (long long)(m0 + row) * K + akq);
        As[0][akq + 0][row] = v.x; As[0][akq + 1][row] = v.y;
        As[0][akq + 2][row] = v.z; As[0][akq + 3][row] = v.w;
        int krow = br0 + it * 8;
        float4 w = *(const float4*)(B + (long long)krow * 256 + n0 + bcq);
        *(float4*)&Bs[0][krow][bcq] = w;
    }
    __syncthreads();

    int buf = 0;
    for (int k0 = 0; k0 < K; k0 += TK) {
        const int kn = k0 + TK;
        if (kn < K) {
            #pragma unroll
            for (int it = 0; it < 2; it++) {
                int row = ar0 + it * 64;
                ra[it] = make_float4(0.f, 0.f, 0.f, 0.f);
                if (m0 + row < M)
                    ra[it] = *(const float4*)(A + (long long)(m0 + row) * K + kn + akq);
                int krow = br0 + it * 8;
                rb[it] = *(const float4*)(B + (long long)(kn + krow) * 256 + n0 + bcq);
            }
        }
        #pragma unroll
        for (int k = 0; k < TK; k++) {
            float4 a0 = *(const float4*)&As[buf][k][tm * 8];
            float4 a1 = *(const float4*)&As[buf][k][tm * 8 + 4];
            // b pairs loaded directly as packed 64-bit values
            ulonglong2 b01 = *(const ulonglong2*)&Bs[buf][k][tn * 8];
            ulonglong2 b23 = *(const ulonglong2*)&Bs[buf][k][tn * 8 + 4];
            unsigned long long bp[4] = {b01.x, b01.y, b23.x, b23.y};
            unsigned long long ad[8];
            ad[0] = f32x2_dup(a0.x); ad[1] = f32x2_dup(a0.y);
            ad[2] = f32x2_dup(a0.z); ad[3] = f32x2_dup(a0.w);
            ad[4] = f32x2_dup(a1.x); ad[5] = f32x2_dup(a1.y);
            ad[6] = f32x2_dup(a1.z); ad[7] = f32x2_dup(a1.w);
            #pragma unroll
            for (int i = 0; i < 8; i++)
                #pragma unroll
                for (int j = 0; j < 4; j++)
                    acc[i][j] = f32x2_fma(ad[i], bp[j], acc[i][j]);
        }
        if (kn < K) {
            int nb = buf ^ 1;
            #pragma unroll
            for (int it = 0; it < 2; it++) {
                int row = ar0 + it * 64;
                As[nb][akq + 0][row] = ra[it].x; As[nb][akq + 1][row] = ra[it].y;
                As[nb][akq + 2][row] = ra[it].z; As[nb][akq + 3][row] = ra[it].w;
                int krow = br0 + it * 8;
                *(float4*)&Bs[nb][krow][bcq] = rb[it];
            }
        }
        __syncthreads();
        buf ^= 1;
    }

    const int c0 = n0 + tn * 8;
    ulonglong2 bias01 = *(const ulonglong2*)(bias + c0);
    ulonglong2 bias23 = *(const ulonglong2*)(bias + c0 + 4);
    unsigned long long bp[4] = {bias01.x, bias01.y, bias23.x, bias23.y};
    #pragma unroll
    for (int i = 0; i < 8; i++) {
        int m = m0 + tm * 8 + i;
        if (m < M) {
            ulonglong2 o01, o23;
            o01.x = f32x2_add(acc[i][0], bp[0]);
            o01.y = f32x2_add(acc[i][1], bp[1]);
            o23.x = f32x2_add(acc[i][2], bp[2]);
            o23.y = f32x2_add(acc[i][3], bp[3]);
            *(ulonglong2*)(C + (long long)m * 256 + c0)     = o01;
            *(ulonglong2*)(C + (long long)m * 256 + c0 + 4) = o23;
        }
    }
}

// ------- fused conv1 CSR + softmax + skip + LN + ELU + conv2 projection ----
__global__ __launch_bounds__(256) void conv1_csr_kernel(
    const float* __restrict__ att1, const float* __restrict__ bias1,
    const float* __restrict__ gamma, const float* __restrict__ beta,
    const float* __restrict__ W2l, const float* __restrict__ b2l,
    const float* __restrict__ W2r, const float* __restrict__ b2r,
    const float* __restrict__ att2, int N)
{
    const int n = blockIdx.x * 8 + (threadIdx.x >> 5);
    const int lane = threadIdx.x & 31;
    if (n >= N) return;

    float attv[8];
    {
        float4 a0 = *(const float4*)(att1 + lane * 8);
        float4 a1 = *(const float4*)(att1 + lane * 8 + 4);
        attv[0]=a0.x; attv[1]=a0.y; attv[2]=a0.z; attv[3]=a0.w;
        attv[4]=a1.x; attv[5]=a1.y; attv[6]=a1.z; attv[7]=a1.w;
    }
    float xr[8];
    {
        const float* p = g_XR1 + (long long)n * HCc + lane * 8;
        float4 r0 = *(const float4*)p;
        float4 r1 = *(const float4*)(p + 4);
        xr[0]=r0.x; xr[1]=r0.y; xr[2]=r0.z; xr[3]=r0.w;
        xr[4]=r1.x; xr[5]=r1.y; xr[6]=r1.z; xr[7]=r1.w;
    }

    float acc[8], den;
    {
        const float* p = g_XL1 + (long long)n * HCc + lane * 8;
        float4 l0 = *(const float4*)p;
        float4 l1 = *(const float4*)(p + 4);
        float xl[8] = {l0.x,l0.y,l0.z,l0.w,l1.x,l1.y,l1.z,l1.w};
        float s = 0.f;
        #pragma unroll
        for (int j = 0; j < 8; j++) {
            float e = xl[j] + xr[j];
            e = e > 0.f ? e : NEG * e;
            s = fmaf(e, attv[j], s);
        }
        s += __shfl_xor_sync(0xffffffffu, s, 1);
        s += __shfl_xor_sync(0xffffffffu, s, 2);
        s += __shfl_xor_sync(0xffffffffu, s, 4);
        float ex = expf(s);
        den = ex;
        #pragma unroll
        for (int j = 0; j < 8; j++) acc[j] = ex * xl[j];
    }

    const int row0 = g_rowptr[n];
    const int row1 = g_rowptr[n + 1];
    int src_next = (row0 < row1) ? g_esrc[row0] : 0;
    for (int i = row0; i < row1; i++) {
        int src = src_next;
        if (i + 1 < row1) src_next = g_esrc[i + 1];
        const float* p = g_XL1 + (long long)src * HCc + lane * 8;
        float4 l0 = *(const float4*)p;
        float4 l1 = *(const float4*)(p + 4);
        float xl[8] = {l0.x,l0.y,l0.z,l0.w,l1.x,l1.y,l1.z,l1.w};
        float s = 0.f;
        #pragma unroll
        for (int j = 0; j < 8; j++) {
            float e = xl[j] + xr[j];
            e = e > 0.f ? e : NEG * e;
            s = fmaf(e, attv[j], s);
        }
        s += __shfl_xor_sync(0xffffffffu, s, 1);
        s += __shfl_xor_sync(0xffffffffu, s, 2);
        s += __shfl_xor_sync(0xffffffffu, s, 4);
        float ex = expf(s);
        den += ex;
        #pragma unroll
        for (int j = 0; j < 8; j++) acc[j] = fmaf(ex, xl[j], acc[j]);
    }

    const float dinv = 1.0f / den;
    float v[8];
    {
        const float* sp = g_SKIP + (long long)n * HCc + lane * 8;
        float4 s0 = *(const float4*)sp;
        float4 s1 = *(const float4*)(sp + 4);
        float4 b0 = *(const float4*)(bias1 + lane * 8);
        float4 b1 = *(const float4*)(bias1 + lane * 8 + 4);
        float sk[8] = {s0.x,s0.y,s0.z,s0.w,s1.x,s1.y,s1.z,s1.w};
        float bb[8] = {b0.x,b0.y,b0.z,b0.w,b1.x,b1.y,b1.z,b1.w};
        #pragma unroll
        for (int j = 0; j < 8; j++) v[j] = acc[j] * dinv + bb[j] + sk[j];
    }

    float t = 0.f;
    #pragma unroll
    for (int j = 0; j < 8; j++) t += v[j];
    #pragma unroll
    for (int o = 16; o > 0; o >>= 1) t += __shfl_xor_sync(0xffffffffu, t, o);
    const float mu = t * (1.0f / 256.0f);
    float t2 = 0.f;
    #pragma unroll
    for (int j = 0; j < 8; j++) { float d = v[j] - mu; t2 = fmaf(d, d, t2); }
    #pragma unroll
    for (int o = 16; o > 0; o >>= 1) t2 += __shfl_xor_sync(0xffffffffu, t2, o);
    const float rstd = rsqrtf(t2 * (1.0f / 256.0f) + 1e-5f);

    float h[8];
    {
        float4 g0 = *(const float4*)(gamma + lane * 8);
        float4 g1 = *(const float4*)(gamma + lane * 8 + 4);
        float4 e0 = *(const float4*)(beta + lane * 8);
        float4 e1 = *(const float4*)(beta + lane * 8 + 4);
        float gg[8] = {g0.x,g0.y,g0.z,g0.w,g1.x,g1.y,g1.z,g1.w};
        float be[8] = {e0.x,e0.y,e0.z,e0.w,e1.x,e1.y,e1.z,e1.w};
        #pragma unroll
        for (int j = 0; j < 8; j++) {
            float hh = (v[j] - mu) * rstd * gg[j] + be[j];
            h[j] = hh > 0.f ? hh : expm1f(hh);
        }
    }

    float p0 = 0.f, p1 = 0.f, p2 = 0.f, p3 = 0.f;
    {
        const float* wl = W2l + lane * 16;
        const float* wr = W2r + lane * 16;
        float4 wl0 = *(const float4*)wl;
        float4 wl1 = *(const float4*)(wl + 4);
        float4 wl2 = *(const float4*)(wl + 8);
        float4 wl3 = *(const float4*)(wl + 12);
        float4 wr0 = *(const float4*)wr;
        float4 wr1 = *(const float4*)(wr + 4);
        float4 wr2 = *(const float4*)(wr + 8);
        float4 wr3 = *(const float4*)(wr + 12);
        float wlv[16] = {wl0.x,wl0.y,wl0.z,wl0.w, wl1.x,wl1.y,wl1.z,wl1.w,
                         wl2.x,wl2.y,wl2.z,wl2.w, wl3.x,wl3.y,wl3.z,wl3.w};
        float wrv[16] = {wr0.x,wr0.y,wr0.z,wr0.w, wr1.x,wr1.y,wr1.z,wr1.w,
                         wr2.x,wr2.y,wr2.z,wr2.w, wr3.x,wr3.y,wr3.z,wr3.w};
        #pragma unroll
        for (int j = 0; j < 8; j++) {
            p0 = fmaf(h[j], wlv[2 * j + 0], p0);
            p1 = fmaf(h[j], wlv[2 * j + 1], p1);
            p2 = fmaf(h[j], wrv[2 * j + 0], p2);
            p3 = fmaf(h[j], wrv[2 * j + 1], p3);
        }
    }
    #pragma unroll
    for (int o = 16; o > 0; o >>= 1) {
        p0 += __shfl_xor_sync(0xffffffffu, p0, o);
        p1 += __shfl_xor_sync(0xffffffffu, p1, o);
        p2 += __shfl_xor_sync(0xffffffffu, p2, o);
        p3 += __shfl_xor_sync(0xffffffffu, p3, o);
    }
    if (lane == 0) {
        float2 xl2, xr2;
        xl2.x = p0 + b2l[0]; xl2.y = p1 + b2l[1];
        xr2.x = p2 + b2r[0]; xr2.y = p3 + b2r[1];
        *(float2*)&g_XL2[n * 2] = xl2;
        *(float2*)&g_XR2[n * 2] = xr2;
    }
}

// ------------- conv2 CSR + final output (one thread per node) -------------
__global__ void conv2_csr_kernel(const float* __restrict__ att2,
                                 const float* __restrict__ bias2,
                                 float* __restrict__ out, int N) {
    int n = blockIdx.x * blockDim.x + threadIdx.x;
    if (n >= N) return;
    const float a0 = att2[0], a1 = att2[1];
    float2 xls = *(const float2*)&g_XL2[n * 2];
    float2 xr  = *(const float2*)&g_XR2[n * 2];
    float e0 = xls.x + xr.x; e0 = e0 > 0.f ? e0 : NEG * e0;
    float e1 = xls.y + xr.y; e1 = e1 > 0.f ? e1 : NEG * e1;
    float ex = expf(fmaf(e0, a0, e1 * a1));
    float den = ex, s0 = ex * xls.x, s1 = ex * xls.y;
    const int row0 = g_rowptr[n], row1 = g_rowptr[n + 1];
    for (int i = row0; i < row1; i++) {
        int src = g_esrc[i];
        float2 xl = *(const float2*)&g_XL2[src * 2];
        float f0 = xl.x + xr.x; f0 = f0 > 0.f ? f0 : NEG * f0;
        float f1 = xl.y + xr.y; f1 = f1 > 0.f ? f1 : NEG * f1;
        float exi = expf(fmaf(f0, a0, f1 * a1));
        den += exi;
        s0 = fmaf(exi, xl.x, s0);
        s1 = fmaf(exi, xl.y, s1);
    }
    float dinv = 1.0f / den;
    float2 o;
    o.x = s0 * dinv + bias2[0];
    o.y = s1 * dinv + bias2[1];
    *(float2*)(out + n * 2) = o;
}

// ---------------------------------------------------------------------------
extern "C" void kernel_launch(void* const* d_in, const int* in_sizes, int n_in,
                              void* d_out, int out_size) {
    const float* x     = (const float*)d_in[0];
    const void*  ei    = d_in[1];
    const float* W1l   = (const float*)d_in[2];
    const float* b1l   = (const float*)d_in[3];
    const float* W1r   = (const float*)d_in[4];
    const float* b1r   = (const float*)d_in[5];
    const float* att1  = (const float*)d_in[6];
    const float* bias1 = (const float*)d_in[7];
    const float* W2l   = (const float*)d_in[8];
    const float* b2l   = (const float*)d_in[9];
    const float* W2r   = (const float*)d_in[10];
    const float* b2r   = (const float*)d_in[11];
    const float* att2  = (const float*)d_in[12];
    const float* bias2 = (const float*)d_in[13];
    const float* Wskip = (const float*)d_in[14];
    const float* bskip = (const float*)d_in[15];
    const float* gamma = (const float*)d_in[16];
    const float* beta  = (const float*)d_in[17];
    float* out = (float*)d_out;

    const int       N = in_sizes[0] / DIN;            // 50000
    const long long E = (long long)in_sizes[1] / 2;   // 800000

    float *dXL1, *dXR1, *dSKIP;
    cudaGetSymbolAddress((void**)&dXL1, g_XL1);
    cudaGetSymbolAddress((void**)&dXR1, g_XR1);
    cudaGetSymbolAddress((void**)&dSKIP, g_SKIP);

    detect_idx_kernel<<<1, 1>>>((const unsigned int*)ei);

    // CSR build
    const int SB = (N + 1023) / 1024;
    zero_deg_kernel<<<(N + 255) / 256, 256>>>(N);
    hist_kernel<<<(int)((E + 255) / 256), 256>>>(ei, E);
    scanA_kernel<<<SB, 1024>>>(N);
    scanB_kernel<<<1, 32>>>(SB);
    scanC_kernel<<<SB, 1024>>>(N);
    scatter_kernel<<<(int)((E + 255) / 256), 256>>>(ei, E);

    // fused triple GEMM with packed FFMA2
    dim3 gg(6, (N + TM - 1) / TM);
    sgemm3_kernel<<<gg, 256>>>(x, W1l, W1r, Wskip, b1l, b1r, bskip,
                               dXL1, dXR1, dSKIP, N, DIN);

    // fused conv1 + epilogue (warp per node, no atomics)
    conv1_csr_kernel<<<(N + 7) / 8, 256>>>(att1, bias1, gamma, beta,
                                           W2l, b2l, W2r, b2r, att2, N);

    // conv2 + final output
    conv2_csr_kernel<<<(N + 255) / 256, 256>>>(att2, bias2, out, N);
}